// round 16
// baseline (speedup 1.0000x reference)
#include <cuda_runtime.h>
#include <cuda_fp16.h>
#include <cstdint>

// LocalDotAttention B=4,H=16,S=2048,D=64 fp32 — mma.sync (HMMA) flash kernel.
// QK: rounded Q x rounded K. PV: rounded W x rounded V.
// fp16x2 epilogue (ex2.approx.f16x2); masked -> bias=-inf -> exp=0.
// 384 threads / 12 warps: mi(4) x ni(3) with N-spans {48,48,32} -> 3 warps
// per SMSP (latency hiding) at UNCHANGED per-SM LDSM/MMA/MUFU totals.
// Pre-pass converts K/V to fp16; cp.async staging, 4-deep ring, stage 2 ahead.

namespace {

constexpr int Ss = 2048;
constexpr int BM = 128;
constexpr int BN = 128;
constexpr int NIT = Ss / BN;
constexpr int NTHR = 384;
constexpr int BH = 64;               // B*H

// fp16 scratch for converted K and V
__device__ __half KH_g[(size_t)BH * Ss * 64];
__device__ __half VH_g[(size_t)BH * Ss * 64];

// smem byte offsets (tiles: 128 rows x 128B = 16KB, swizzled fp16)
constexpr int SM_QH   = 0;
constexpr int SM_KBUF = 16384;        // 4 buffers x {KH, VH} = 4 x 32768
constexpr int KB_STRIDE = 32768;
constexpr int KB_KH = 0;
constexpr int KB_VH = 16384;
constexpr int SM_BIAS = 147456;       // 4 x 64 half2 (512B stride)
constexpr int SM_DEC  = 149504;       // 4 x 256 half2 (1024B stride)
constexpr int SM_L    = 153600;       // 3 x 128 f32 (per ni group)
constexpr int SM_OX   = SM_KBUF;      // reused for O exchange after main loop
constexpr int OXS = 68;               // f32 stride for O exchange rows
constexpr int OX_NI = 34816;          // bytes per exporting ni group
constexpr int SM_TOTAL = 155648;

__device__ __forceinline__ uint32_t smem_u32(const void* p) {
    uint32_t a;
    asm("{ .reg .u64 t; cvta.to.shared.u64 t, %1; cvt.u32.u64 %0, t; }" : "=r"(a) : "l"(p));
    return a;
}
__device__ __forceinline__ float ex2(float x) {
    float r; asm("ex2.approx.ftz.f32 %0, %1;" : "=f"(r) : "f"(x)); return r;
}
__device__ __forceinline__ float lds32(uint32_t a) {
    float v; asm volatile("ld.shared.f32 %0, [%1];" : "=f"(v) : "r"(a)); return v;
}
__device__ __forceinline__ void sts32(uint32_t a, float v) {
    asm volatile("st.shared.f32 [%0], %1;" :: "r"(a), "f"(v));
}
__device__ __forceinline__ void sts32u(uint32_t a, uint32_t v) {
    asm volatile("st.shared.b32 [%0], %1;" :: "r"(a), "r"(v));
}
__device__ __forceinline__ uint32_t lds32u(uint32_t a) {
    uint32_t v; asm volatile("ld.shared.b32 %0, [%1];" : "=r"(v) : "r"(a)); return v;
}
__device__ __forceinline__ void sts64f(uint32_t a, float x, float y) {
    asm volatile("st.shared.v2.f32 [%0], {%1,%2};" :: "r"(a), "f"(x), "f"(y));
}
__device__ __forceinline__ float2 lds64f(uint32_t a) {
    float2 v; asm volatile("ld.shared.v2.f32 {%0,%1}, [%2];" : "=f"(v.x), "=f"(v.y) : "r"(a));
    return v;
}
// pack (lo, hi) fp32 -> half2 (first asm source lands in HIGH half)
__device__ __forceinline__ uint32_t pack_h2(float lo, float hi) {
    uint32_t d;
    asm("cvt.rn.f16x2.f32 %0, %1, %2;" : "=r"(d) : "f"(hi), "f"(lo));
    return d;
}
__device__ __forceinline__ uint32_t h2ex2(uint32_t x) {
    uint32_t d;
    asm("ex2.approx.f16x2 %0, %1;" : "=r"(d) : "r"(x));
    return d;
}
__device__ __forceinline__ uint32_t h2fma(uint32_t a, uint32_t b, uint32_t c) {
    uint32_t d;
    asm("fma.rn.f16x2 %0, %1, %2, %3;" : "=r"(d) : "r"(a), "r"(b), "r"(c));
    return d;
}
__device__ __forceinline__ uint32_t h2mul(uint32_t a, uint32_t b) {
    uint32_t d;
    asm("mul.f16x2 %0, %1, %2;" : "=r"(d) : "r"(a), "r"(b));
    return d;
}
__device__ __forceinline__ uint32_t h2add(uint32_t a, uint32_t b) {
    uint32_t d;
    asm("add.f16x2 %0, %1, %2;" : "=r"(d) : "r"(a), "r"(b));
    return d;
}

#define CP_ASYNC16(dst, src) \
    asm volatile("cp.async.cg.shared.global [%0], [%1], 16;" :: "r"(dst), "l"(src))
#define CP_COMMIT() asm volatile("cp.async.commit_group;" ::: "memory")
#define CP_WAIT0()  asm volatile("cp.async.wait_group 0;" ::: "memory")

#define LDSM_X4(r0, r1, r2, r3, addr) \
    asm volatile("ldmatrix.sync.aligned.m8n8.x4.shared.b16 {%0,%1,%2,%3}, [%4];" \
        : "=r"(r0), "=r"(r1), "=r"(r2), "=r"(r3) : "r"(addr))
#define LDSM_X4T(r0, r1, r2, r3, addr) \
    asm volatile("ldmatrix.sync.aligned.m8n8.x4.trans.shared.b16 {%0,%1,%2,%3}, [%4];" \
        : "=r"(r0), "=r"(r1), "=r"(r2), "=r"(r3) : "r"(addr))
#define MMA16816(d, a, b0, b1) \
    asm volatile("mma.sync.aligned.m16n8k16.row.col.f32.f16.f16.f32 " \
        "{%0,%1,%2,%3},{%4,%5,%6,%7},{%8,%9},{%0,%1,%2,%3};" \
        : "+f"((d)[0]), "+f"((d)[1]), "+f"((d)[2]), "+f"((d)[3]) \
        : "r"((a)[0]), "r"((a)[1]), "r"((a)[2]), "r"((a)[3]), "r"(b0), "r"(b1))

// swizzled byte offset within a 128-row x 128-byte tile: row r, 16B unit u (0..7)
__device__ __forceinline__ uint32_t sw(int r, int u) {
    return (uint32_t)(r * 128 + ((u ^ (r & 7)) << 4));
}

// ---- pre-pass: convert K/V fp32 -> fp16 scratch (bit-identical rounding) ----
__global__ void cvt_kv_kernel(const float4* __restrict__ K,
                              const float4* __restrict__ V)
{
    size_t i = (size_t)blockIdx.x * blockDim.x + threadIdx.x;   // one float4
    const float4* src = blockIdx.y ? V : K;
    __half* dst = blockIdx.y ? VH_g : KH_g;
    float4 v = src[i];
    half2 a = __floats2half2_rn(v.x, v.y);
    half2 b = __floats2half2_rn(v.z, v.w);
    uint2 u;
    u.x = *reinterpret_cast<uint32_t*>(&a);
    u.y = *reinterpret_cast<uint32_t*>(&b);
    *reinterpret_cast<uint2*>(dst + i * 4) = u;
}

__global__ __launch_bounds__(NTHR, 1) void attn_hmma_kernel(
    const float* __restrict__ Q,
    const int* __restrict__ mask,
    float* __restrict__ O)
{
    extern __shared__ char smem[];
    const uint32_t sb = smem_u32(smem);

    const int tid  = threadIdx.x;
    const int lane = tid & 31;
    const int wid  = tid >> 5;
    const int mi   = wid & 3;        // M group: rows 32*mi
    const int ni   = wid >> 2;       // N group: 0,1 -> 48 cols; 2 -> 32 cols
    const int coff = ni * 48;        // first S-col of this warp's span
    const int nch  = (ni == 2) ? 2 : 3;   // 16-col chunks in span
    const int bh   = blockIdx.y;
    const int b    = bh >> 4;
    const int q0   = blockIdx.x * BM;

    const float L2E  = 1.4426950408889634f;
    const float cL2E = (2.0f / ((float)Ss * (float)Ss)) * L2E;
    const uint32_t L2E2 = pack_h2(L2E, L2E);

    const int lrow = (lane & 7) + (((lane >> 3) & 1) << 3);
    const int luni = (lane >> 4);

    const __half* Kh = KH_g + (size_t)bh * Ss * 64;
    const __half* Vh = VH_g + (size_t)bh * Ss * 64;

    // ---- staging: cp.async K/V tiles + half2 bias + half2 decay-pair tables ----
    auto stage_kv = [&](int it) {
        const int kb  = it * BN;
        const uint32_t kbuf = sb + SM_KBUF + (uint32_t)(it & 3) * KB_STRIDE;
        const __half* Ksrc = Kh + (size_t)kb * 64;
        const __half* Vsrc = Vh + (size_t)kb * 64;
        #pragma unroll
        for (int p = 0; p < 3; ++p) {            // 1024 16B chunks per tile
            int c = p * NTHR + tid;
            if (c < 1024) {
                int r = c >> 3, u = c & 7;
                uint32_t off = sw(r, u);
                CP_ASYNC16(kbuf + KB_KH + off, Ksrc + r * 64 + u * 8);
                CP_ASYNC16(kbuf + KB_VH + off, Vsrc + r * 64 + u * 8);
            }
        }
        // B2[j] = half2(bias[2j] lo, bias[2j+1] hi); masked -> -inf
        if (tid < 64) {
            int m0 = mask[b * Ss + kb + 2 * tid];
            int m1 = mask[b * Ss + kb + 2 * tid + 1];
            uint32_t v = (m0 ? 0xFC00u : 0u) | (m1 ? 0xFC000000u : 0u);
            sts32u(sb + SM_BIAS + (it & 3) * 512 + tid * 4, v);
        }
        // DR2[j] = half2(dec[j+1] lo, dec[j] hi)  (pre-swapped pair table)
        if (tid < 256) {
            float d0 = (float)((q0 - kb) + tid - 127);
            float d1 = d0 + 1.0f;
            float f0 = ex2(-d0 * d0 * cL2E);
            float f1 = ex2(-d1 * d1 * cL2E);
            sts32u(sb + SM_DEC + (it & 3) * 1024 + tid * 4, pack_h2(f1, f0));
        }
        CP_COMMIT();
    };

    // ---- stage Q (scaled by 1/8, rounded fp16, swizzled) + first 2 K/V buffers ----
    {
        const float4* Qg = reinterpret_cast<const float4*>(Q + ((size_t)bh * Ss + q0) * 64);
        #pragma unroll
        for (int p = 0; p < 6; ++p) {
            int idx = p * NTHR + tid;
            if (idx < 2048) {
                int r = idx >> 4, g = idx & 15;
                uint32_t off = sw(r, g >> 1) + ((g & 1) << 3);
                float4 v = Qg[idx];
                uint32_t h01 = pack_h2(v.x * 0.125f, v.y * 0.125f);
                uint32_t h23 = pack_h2(v.z * 0.125f, v.w * 0.125f);
                asm volatile("st.shared.v2.b32 [%0], {%1,%2};"
                    :: "r"(sb + SM_QH + off), "r"(h01), "r"(h23));
            }
        }
    }
    stage_kv(0);
    stage_kv(1);
    CP_WAIT0();
    __syncthreads();

    // ---- hoist Q fragments (loop-invariant): 4 kt x 2 m x 4 regs ----
    uint32_t qh[4][2][4];
    #pragma unroll
    for (int kt = 0; kt < 4; ++kt)
        #pragma unroll
        for (int m = 0; m < 2; ++m) {
            int rr = 32 * mi + 16 * m + lrow;
            uint32_t off = sw(rr, 2 * kt + luni);
            LDSM_X4(qh[kt][m][0], qh[kt][m][1], qh[kt][m][2], qh[kt][m][3],
                    sb + SM_QH + off);
        }

    float Oacc[2][8][4];
    #pragma unroll
    for (int m = 0; m < 2; ++m)
        #pragma unroll
        for (int n = 0; n < 8; ++n)
            #pragma unroll
            for (int j = 0; j < 4; ++j) Oacc[m][n][j] = 0.f;
    float lacc[2][2] = {{0.f, 0.f}, {0.f, 0.f}};

    #pragma unroll 1
    for (int it = 0; it < NIT; ++it) {
        const uint32_t kbuf = sb + SM_KBUF + (uint32_t)(it & 3) * KB_STRIDE;
        const uint32_t biasA = sb + SM_BIAS + (it & 3) * 512;
        const uint32_t decA  = sb + SM_DEC + (it & 3) * 1024;

        #pragma unroll 1
        for (int g = 0; g < nch; ++g) {
            const int cg = coff + 16 * g;       // chunk's first S-col
            const int rr = cg + lrow;           // K/V tile row for ldmatrix

            // ---- QK for this 16-col chunk ----
            float S[2][2][4];
            #pragma unroll
            for (int m = 0; m < 2; ++m)
                #pragma unroll
                for (int p = 0; p < 2; ++p)
                    #pragma unroll
                    for (int j = 0; j < 4; ++j) S[m][p][j] = 0.f;
            #pragma unroll
            for (int kt = 0; kt < 4; ++kt) {
                uint32_t off = sw(rr, 2 * kt + luni);
                uint32_t kh[4];
                LDSM_X4(kh[0], kh[1], kh[2], kh[3], kbuf + KB_KH + off);
                #pragma unroll
                for (int m = 0; m < 2; ++m) {
                    MMA16816(S[m][0], qh[kt][m], kh[0], kh[2]);
                    MMA16816(S[m][1], qh[kt][m], kh[1], kh[3]);
                }
            }

            if (g == 0 && it + 2 < NIT) stage_kv(it + 2);

            // ---- fp16x2 epilogue for this chunk ----
            uint32_t wh[2][4];
            uint32_t lh[2][2] = {{0u, 0u}, {0u, 0u}};
            #pragma unroll
            for (int p = 0; p < 2; ++p) {
                const int c0 = cg + 8 * p + 2 * (lane & 3);
                const uint32_t b2 = lds32u(biasA + ((c0 >> 1) << 2));
                const int i00 = (32 * mi + (lane >> 2)) - c0 + 127;
                #pragma unroll
                for (int m = 0; m < 2; ++m) {
                    float* s = S[m][p];
                    uint32_t x0 = h2fma(pack_h2(s[0], s[1]), L2E2, b2);
                    uint32_t x1 = h2fma(pack_h2(s[2], s[3]), L2E2, b2);
                    uint32_t e0 = h2ex2(x0);
                    uint32_t e1 = h2ex2(x1);
                    lh[m][0] = h2add(lh[m][0], e0);
                    lh[m][1] = h2add(lh[m][1], e1);
                    const int ib = i00 + 16 * m;
                    wh[m][2*p]   = h2mul(e0, lds32u(decA + (ib - 1) * 4));
                    wh[m][2*p+1] = h2mul(e1, lds32u(decA + (ib + 7) * 4));
                }
            }
            #pragma unroll
            for (int m = 0; m < 2; ++m)
                #pragma unroll
                for (int h = 0; h < 2; ++h) {
                    half2 v = *reinterpret_cast<half2*>(&lh[m][h]);
                    float2 f = __half22float2(v);
                    lacc[m][h] += f.x + f.y;
                }

            // ---- PV for this chunk (reduction over its 16 S-cols) ----
            #pragma unroll
            for (int jg = 0; jg < 4; ++jg) {
                uint32_t off = sw(rr, 2 * jg + luni);
                uint32_t t0, t1, t2, t3;
                LDSM_X4T(t0, t1, t2, t3, kbuf + KB_VH + off);
                #pragma unroll
                for (int m = 0; m < 2; ++m) {
                    MMA16816(Oacc[m][2*jg],   wh[m], t0, t1);
                    MMA16816(Oacc[m][2*jg+1], wh[m], t2, t3);
                }
            }
        }

        // every 2 iters: drain cp.async groups, publish buffers, bound drift
        if (it & 1) { CP_WAIT0(); __syncthreads(); }
    }

    // ---- reduce l across lanes sharing a row, store per-row partials ----
    #pragma unroll
    for (int m = 0; m < 2; ++m)
        #pragma unroll
        for (int h = 0; h < 2; ++h) {
            float v = lacc[m][h];
            v += __shfl_xor_sync(0xFFFFFFFFu, v, 1);
            v += __shfl_xor_sync(0xFFFFFFFFu, v, 2);
            if ((lane & 3) == 0) {
                int row = 32 * mi + 16 * m + 8 * h + (lane >> 2);
                sts32(sb + SM_L + ni * 512 + row * 4, v);
            }
        }

    // ---- ni 1,2 export O partials to smem ----
    if (ni != 0) {
        const uint32_t oxb = sb + SM_OX + (uint32_t)(ni - 1) * OX_NI;
        #pragma unroll
        for (int m = 0; m < 2; ++m)
            #pragma unroll
            for (int nt = 0; nt < 8; ++nt) {
                int rl = 32 * mi + 16 * m + (lane >> 2);
                int c  = 8 * nt + 2 * (lane & 3);
                sts64f(oxb + (rl * OXS + c) * 4, Oacc[m][nt][0], Oacc[m][nt][1]);
                sts64f(oxb + ((rl + 8) * OXS + c) * 4, Oacc[m][nt][2], Oacc[m][nt][3]);
            }
    }
    __syncthreads();

    // ---- ni 0 combines, normalizes, writes gmem ----
    if (ni == 0) {
        #pragma unroll
        for (int m = 0; m < 2; ++m) {
            int rl  = 16 * m + (lane >> 2);
            int rg0 = 32 * mi + rl;
            float l0 = 0.f, l1 = 0.f;
            #pragma unroll
            for (int gr = 0; gr < 3; ++gr) {
                l0 += lds32(sb + SM_L + gr * 512 + rg0 * 4);
                l1 += lds32(sb + SM_L + gr * 512 + (rg0 + 8) * 4);
            }
            float inv0 = 1.0f / l0;
            float inv1 = 1.0f / l1;
            #pragma unroll
            for (int nt = 0; nt < 8; ++nt) {
                int c = 8 * nt + 2 * (lane & 3);
                float s0x = Oacc[m][nt][0], s0y = Oacc[m][nt][1];
                float s1x = Oacc[m][nt][2], s1y = Oacc[m][nt][3];
                #pragma unroll
                for (int gr = 0; gr < 2; ++gr) {
                    const uint32_t oxb = sb + SM_OX + (uint32_t)gr * OX_NI;
                    float2 p0 = lds64f(oxb + (rg0 * OXS + c) * 4);
                    float2 p1 = lds64f(oxb + ((rg0 + 8) * OXS + c) * 4);
                    s0x += p0.x; s0y += p0.y;
                    s1x += p1.x; s1y += p1.y;
                }
                float2* og0 = reinterpret_cast<float2*>(
                    O + ((size_t)bh * Ss + q0 + rg0) * 64 + c);
                float2* og1 = reinterpret_cast<float2*>(
                    O + ((size_t)bh * Ss + q0 + rg0 + 8) * 64 + c);
                *og0 = make_float2(s0x * inv0, s0y * inv0);
                *og1 = make_float2(s1x * inv1, s1y * inv1);
            }
        }
    }
}

} // namespace

extern "C" void kernel_launch(void* const* d_in, const int* in_sizes, int n_in,
                              void* d_out, int out_size)
{
    const float* Q = (const float*)d_in[0];
    const float* K = (const float*)d_in[1];
    const float* V = (const float*)d_in[2];
    const int*   mask = (const int*)d_in[3];
    float* O = (float*)d_out;

    // pre-pass: fp32 -> fp16 conversion of K and V into scratch
    {
        dim3 grid((unsigned)(((size_t)BH * Ss * 64 / 4) / 256), 2);
        cvt_kv_kernel<<<grid, 256>>>(reinterpret_cast<const float4*>(K),
                                     reinterpret_cast<const float4*>(V));
    }

    cudaFuncSetAttribute(attn_hmma_kernel, cudaFuncAttributeMaxDynamicSharedMemorySize, SM_TOTAL);
    dim3 grid(Ss / BM, BH);
    attn_hmma_kernel<<<grid, NTHR, SM_TOTAL>>>(Q, mask, O);
}

// round 17
// speedup vs baseline: 1.5719x; 1.5719x over previous
#include <cuda_runtime.h>
#include <cuda_fp16.h>
#include <cstdint>

// LocalDotAttention B=4,H=16,S=2048,D=64 fp32 — mask-compacted HMMA flash kernel.
// mask (per b,k; ~50% ones) zeroes columns EXACTLY (exp(-inf)=0), so the
// pre-pass compacts K/V to the unmasked columns: the k-loop halves (~8-9 tiles).
// QK: rounded Q(x0.125*log2e) x rounded K. PV: rounded W x rounded V.
// Decay computed in-epilogue from compacted column origins:
//   t = (r - s_orig)*sqrt(c*log2e);  dec = ex2.f32(-t^2)  (== R14 table values).
// Pad columns: bias=-inf -> e=0; K/V pad rows zeroed; kos pad -> dec=0.
// 256 threads, warp tile M32xN64, cp.async staging, 4-ring, stage 2 ahead.

namespace {

constexpr int Ss = 2048;
constexpr int BM = 128;
constexpr int BN = 128;
constexpr int NTHR = 256;
constexpr int BH = 64;               // B*H
constexpr int SROWS = 2176;          // compacted rows alloc (2048 + pad)

constexpr float L2E   = 1.4426950408889634f;
constexpr float QSC   = 0.18033688011112042f;   // 0.125 * log2(e)
constexpr float SCL_F = 8.294342e-4f;           // sqrt((2/S^2) * log2(e))
constexpr float KOS_PAD = 24.883026f;           // 3e4 * SCL_F -> dec = 0

// compacted fp16 scratch + per-column tables
__device__ __align__(16) __half KC_g[(size_t)BH * SROWS * 64];
__device__ __align__(16) __half VC_g[(size_t)BH * SROWS * 64];
__device__ __align__(16) float  KOS_g[4 * SROWS];
__device__ __align__(16) unsigned short BIASH_g[4 * SROWS];
__device__ int PFX_g[4 * Ss];
__device__ int CNT_g[4];

// smem byte offsets
constexpr int SM_QH   = 0;            // 16KB
constexpr int SM_KBUF = 16384;        // 4 x {KH,VH} = 4 x 32768
constexpr int KB_STRIDE = 32768;
constexpr int KB_KH = 0;
constexpr int KB_VH = 16384;
constexpr int SM_KOS  = 147456;       // 4 x 512B
constexpr int SM_BIA  = 149504;       // 4 x 256B
constexpr int SM_L    = 150528;       // 2 x 512B
constexpr int SM_OX   = SM_KBUF;      // reused after main loop
constexpr int OXS = 68;
constexpr int SM_TOTAL = 151552;

__device__ __forceinline__ uint32_t smem_u32(const void* p) {
    uint32_t a;
    asm("{ .reg .u64 t; cvta.to.shared.u64 t, %1; cvt.u32.u64 %0, t; }" : "=r"(a) : "l"(p));
    return a;
}
__device__ __forceinline__ float ex2f(float x) {
    float r; asm("ex2.approx.ftz.f32 %0, %1;" : "=f"(r) : "f"(x)); return r;
}
__device__ __forceinline__ float lds32(uint32_t a) {
    float v; asm volatile("ld.shared.f32 %0, [%1];" : "=f"(v) : "r"(a)); return v;
}
__device__ __forceinline__ void sts32(uint32_t a, float v) {
    asm volatile("st.shared.f32 [%0], %1;" :: "r"(a), "f"(v));
}
__device__ __forceinline__ uint32_t lds32u(uint32_t a) {
    uint32_t v; asm volatile("ld.shared.b32 %0, [%1];" : "=r"(v) : "r"(a)); return v;
}
__device__ __forceinline__ void sts64f(uint32_t a, float x, float y) {
    asm volatile("st.shared.v2.f32 [%0], {%1,%2};" :: "r"(a), "f"(x), "f"(y));
}
__device__ __forceinline__ float2 lds64f(uint32_t a) {
    float2 v; asm volatile("ld.shared.v2.f32 {%0,%1}, [%2];" : "=f"(v.x), "=f"(v.y) : "r"(a));
    return v;
}
// pack (lo, hi) fp32 -> half2
__device__ __forceinline__ uint32_t pack_h2(float lo, float hi) {
    uint32_t d;
    asm("cvt.rn.f16x2.f32 %0, %1, %2;" : "=r"(d) : "f"(hi), "f"(lo));
    return d;
}
__device__ __forceinline__ uint32_t h2ex2(uint32_t x) {
    uint32_t d; asm("ex2.approx.f16x2 %0, %1;" : "=r"(d) : "r"(x)); return d;
}
__device__ __forceinline__ uint32_t h2mul(uint32_t a, uint32_t b) {
    uint32_t d; asm("mul.f16x2 %0, %1, %2;" : "=r"(d) : "r"(a), "r"(b)); return d;
}
__device__ __forceinline__ uint32_t h2add(uint32_t a, uint32_t b) {
    uint32_t d; asm("add.f16x2 %0, %1, %2;" : "=r"(d) : "r"(a), "r"(b)); return d;
}

#define CP_ASYNC16(dst, src) \
    asm volatile("cp.async.cg.shared.global [%0], [%1], 16;" :: "r"(dst), "l"(src))
#define CP_COMMIT() asm volatile("cp.async.commit_group;" ::: "memory")
#define CP_WAIT0()  asm volatile("cp.async.wait_group 0;" ::: "memory")

#define LDSM_X4(r0, r1, r2, r3, addr) \
    asm volatile("ldmatrix.sync.aligned.m8n8.x4.shared.b16 {%0,%1,%2,%3}, [%4];" \
        : "=r"(r0), "=r"(r1), "=r"(r2), "=r"(r3) : "r"(addr))
#define LDSM_X4T(r0, r1, r2, r3, addr) \
    asm volatile("ldmatrix.sync.aligned.m8n8.x4.trans.shared.b16 {%0,%1,%2,%3}, [%4];" \
        : "=r"(r0), "=r"(r1), "=r"(r2), "=r"(r3) : "r"(addr))
#define MMA16816(d, a, b0, b1) \
    asm volatile("mma.sync.aligned.m16n8k16.row.col.f32.f16.f16.f32 " \
        "{%0,%1,%2,%3},{%4,%5,%6,%7},{%8,%9},{%0,%1,%2,%3};" \
        : "+f"((d)[0]), "+f"((d)[1]), "+f"((d)[2]), "+f"((d)[3]) \
        : "r"((a)[0]), "r"((a)[1]), "r"((a)[2]), "r"((a)[3]), "r"(b0), "r"(b1))

__device__ __forceinline__ uint32_t sw(int r, int u) {
    return (uint32_t)(r * 128 + ((u ^ (r & 7)) << 4));
}

// ---- pre-pass 1: per-batch exclusive prefix of unmasked columns ----
__global__ void scan_kernel(const int* __restrict__ mask)
{
    const int b = blockIdx.x;
    const int t = threadIdx.x;           // 0..1023
    const int lane = t & 31, w = t >> 5;
    int v0 = (mask[b * Ss + 2 * t] == 0) ? 1 : 0;
    int v1 = (mask[b * Ss + 2 * t + 1] == 0) ? 1 : 0;
    int tot = v0 + v1;
    int x = tot;
    #pragma unroll
    for (int off = 1; off < 32; off <<= 1) {
        int y = __shfl_up_sync(0xFFFFFFFFu, x, off);
        if (lane >= off) x += y;
    }
    __shared__ int wsum[32];
    if (lane == 31) wsum[w] = x;
    __syncthreads();
    if (w == 0) {
        int s = wsum[lane];
        #pragma unroll
        for (int off = 1; off < 32; off <<= 1) {
            int y = __shfl_up_sync(0xFFFFFFFFu, s, off);
            if (lane >= off) s += y;
        }
        wsum[lane] = s;
    }
    __syncthreads();
    int incl = x + ((w > 0) ? wsum[w - 1] : 0);
    int excl = incl - tot;
    PFX_g[b * Ss + 2 * t] = excl;
    PFX_g[b * Ss + 2 * t + 1] = excl + v0;
    if (t == 1023) CNT_g[b] = incl;
}

// ---- pre-pass 2: init per-column tables to pad values ----
__global__ void init_kernel()
{
    int i = blockIdx.x * 256 + threadIdx.x;
    if (i < 4 * SROWS) {
        KOS_g[i] = KOS_PAD;
        BIASH_g[i] = 0xFC00;   // half(-inf)
    }
}

// ---- pre-pass 3: gather unmasked K/V rows -> compacted fp16 ----
__global__ void gather_kernel(const float* __restrict__ K,
                              const float* __restrict__ V,
                              const int* __restrict__ mask)
{
    const int bh = blockIdx.y;
    const int b  = bh >> 4;
    const int s  = blockIdx.x * 8 + (threadIdx.x >> 5);
    const int lane = threadIdx.x & 31;
    if (mask[b * Ss + s] != 0) return;
    const int j = PFX_g[b * Ss + s];
    const float2 kv = *reinterpret_cast<const float2*>(
        K + ((size_t)bh * Ss + s) * 64 + lane * 2);
    const float2 vv = *reinterpret_cast<const float2*>(
        V + ((size_t)bh * Ss + s) * 64 + lane * 2);
    *reinterpret_cast<half2*>(KC_g + ((size_t)bh * SROWS + j) * 64 + lane * 2) =
        __floats2half2_rn(kv.x, kv.y);
    *reinterpret_cast<half2*>(VC_g + ((size_t)bh * SROWS + j) * 64 + lane * 2) =
        __floats2half2_rn(vv.x, vv.y);
    if (lane == 0 && (bh & 15) == 0) {
        KOS_g[b * SROWS + j] = (float)s * SCL_F;
        BIASH_g[b * SROWS + j] = 0;    // half(+0)
    }
}

// ---- pre-pass 4: zero the pad rows of compacted K/V ----
__global__ void pad_kernel()
{
    const int bh = blockIdx.x;
    const int b  = bh >> 4;
    const int row = CNT_g[b] + (threadIdx.x >> 3);   // 128 pad rows
    const int q   = threadIdx.x & 7;
    if (row < SROWS) {
        uint4 z = make_uint4(0u, 0u, 0u, 0u);
        *reinterpret_cast<uint4*>(KC_g + ((size_t)bh * SROWS + row) * 64 + q * 8) = z;
        *reinterpret_cast<uint4*>(VC_g + ((size_t)bh * SROWS + row) * 64 + q * 8) = z;
    }
}

__global__ __launch_bounds__(NTHR, 1) void attn_hmma_kernel(
    const float* __restrict__ Q,
    float* __restrict__ O)
{
    extern __shared__ char smem[];
    const uint32_t sb = smem_u32(smem);

    const int tid  = threadIdx.x;
    const int lane = tid & 31;
    const int wid  = tid >> 5;
    const int mi   = wid & 3;        // M group: rows 32*mi
    const int ni   = wid >> 2;       // N group: S-cols 64*ni
    const int bh   = blockIdx.y;
    const int b    = bh >> 4;
    const int q0   = blockIdx.x * BM;

    const int cnt = CNT_g[b];
    const int nit = (cnt + 127) >> 7;

    const int lrow = (lane & 7) + (((lane >> 3) & 1) << 3);
    const int luni = (lane >> 4);

    const __half* Kh = KC_g + (size_t)bh * SROWS * 64;
    const __half* Vh = VC_g + (size_t)bh * SROWS * 64;
    const float*  kosg = KOS_g + b * SROWS;
    const unsigned short* biag = BIASH_g + b * SROWS;

    // ---- staging: cp.async K/V tiles + kos (fp32) + bias (half) ----
    auto stage_kv = [&](int it) {
        const int kb  = it * BN;
        const uint32_t kbuf = sb + SM_KBUF + (uint32_t)(it & 3) * KB_STRIDE;
        const __half* Ksrc = Kh + (size_t)kb * 64;
        const __half* Vsrc = Vh + (size_t)kb * 64;
        #pragma unroll
        for (int p = 0; p < 4; ++p) {
            int c = p * NTHR + tid;
            int r = c >> 3, u = c & 7;
            uint32_t off = sw(r, u);
            CP_ASYNC16(kbuf + KB_KH + off, Ksrc + r * 64 + u * 8);
            CP_ASYNC16(kbuf + KB_VH + off, Vsrc + r * 64 + u * 8);
        }
        if (tid < 32) {
            CP_ASYNC16(sb + SM_KOS + (it & 3) * 512 + tid * 16, kosg + kb + tid * 4);
        } else if (tid < 48) {
            CP_ASYNC16(sb + SM_BIA + (it & 3) * 256 + (tid - 32) * 16,
                       biag + kb + (tid - 32) * 8);
        }
        CP_COMMIT();
    };

    // ---- stage Q (scaled by 0.125*log2e, rounded fp16, swizzled) ----
    {
        const float4* Qg = reinterpret_cast<const float4*>(Q + ((size_t)bh * Ss + q0) * 64);
        #pragma unroll
        for (int p = 0; p < 8; ++p) {
            int idx = p * NTHR + tid;
            int r = idx >> 4, g = idx & 15;
            uint32_t off = sw(r, g >> 1) + ((g & 1) << 3);
            float4 v = Qg[idx];
            uint32_t h01 = pack_h2(v.x * QSC, v.y * QSC);
            uint32_t h23 = pack_h2(v.z * QSC, v.w * QSC);
            asm volatile("st.shared.v2.b32 [%0], {%1,%2};"
                :: "r"(sb + SM_QH + off), "r"(h01), "r"(h23));
        }
    }
    stage_kv(0);
    if (nit > 1) stage_kv(1);
    CP_WAIT0();
    __syncthreads();

    // ---- hoist Q fragments ----
    uint32_t qh[4][2][4];
    #pragma unroll
    for (int kt = 0; kt < 4; ++kt)
        #pragma unroll
        for (int m = 0; m < 2; ++m) {
            int rr = 32 * mi + 16 * m + lrow;
            uint32_t off = sw(rr, 2 * kt + luni);
            LDSM_X4(qh[kt][m][0], qh[kt][m][1], qh[kt][m][2], qh[kt][m][3],
                    sb + SM_QH + off);
        }

    // row*scl constants for decay
    float rsc[2][2];
    #pragma unroll
    for (int m = 0; m < 2; ++m)
        #pragma unroll
        for (int h = 0; h < 2; ++h)
            rsc[m][h] = (float)(q0 + 32 * mi + 16 * m + 8 * h + (lane >> 2)) * SCL_F;

    float Oacc[2][8][4];
    #pragma unroll
    for (int m = 0; m < 2; ++m)
        #pragma unroll
        for (int n = 0; n < 8; ++n)
            #pragma unroll
            for (int j = 0; j < 4; ++j) Oacc[m][n][j] = 0.f;
    float lacc[2][2] = {{0.f, 0.f}, {0.f, 0.f}};

    #pragma unroll 1
    for (int it = 0; it < nit; ++it) {
        const uint32_t kbuf = sb + SM_KBUF + (uint32_t)(it & 3) * KB_STRIDE;
        const uint32_t kosA = sb + SM_KOS + (it & 3) * 512;
        const uint32_t biaA = sb + SM_BIA + (it & 3) * 256;

        // ---- S = Q.K^T ----
        float Sacc[2][8][4];
        #pragma unroll
        for (int m = 0; m < 2; ++m)
            #pragma unroll
            for (int n = 0; n < 8; ++n)
                #pragma unroll
                for (int j = 0; j < 4; ++j) Sacc[m][n][j] = 0.f;

        #pragma unroll
        for (int kt = 0; kt < 4; ++kt) {
            #pragma unroll
            for (int ng = 0; ng < 4; ++ng) {
                int rr = 64 * ni + 16 * ng + lrow;
                uint32_t off = sw(rr, 2 * kt + luni);
                uint32_t kh[4];
                LDSM_X4(kh[0], kh[1], kh[2], kh[3], kbuf + KB_KH + off);
                #pragma unroll
                for (int m = 0; m < 2; ++m) {
                    MMA16816(Sacc[m][2*ng],   qh[kt][m], kh[0], kh[2]);
                    MMA16816(Sacc[m][2*ng+1], qh[kt][m], kh[1], kh[3]);
                }
            }
        }

        if (it + 2 < nit) stage_kv(it + 2);

        // ---- epilogue + PV ----
        uint32_t lh[2][2] = {{0u, 0u}, {0u, 0u}};
        #pragma unroll
        for (int kt2 = 0; kt2 < 4; ++kt2) {
            uint32_t wh[2][4];
            #pragma unroll
            for (int p = 0; p < 2; ++p) {
                const int nt = 2 * kt2 + p;
                const int c0 = 64 * ni + 8 * nt + 2 * (lane & 3);
                const uint32_t b2 = lds32u(biaA + c0 * 2);
                const float2 kp = lds64f(kosA + c0 * 4);
                #pragma unroll
                for (int m = 0; m < 2; ++m) {
                    float* s = Sacc[m][nt];
                    // e = 2^(s + bias)   (s already includes log2e via Q scale)
                    uint32_t x0 = h2add(pack_h2(s[0], s[1]), b2);
                    uint32_t x1 = h2add(pack_h2(s[2], s[3]), b2);
                    uint32_t e0 = h2ex2(x0);
                    uint32_t e1 = h2ex2(x1);
                    lh[m][0] = h2add(lh[m][0], e0);
                    lh[m][1] = h2add(lh[m][1], e1);
                    // decay from compacted origins: dec = 2^(-t^2)
                    float t00 = rsc[m][0] - kp.x, t01 = rsc[m][0] - kp.y;
                    float t10 = rsc[m][1] - kp.x, t11 = rsc[m][1] - kp.y;
                    float d00 = ex2f(-t00 * t00), d01 = ex2f(-t01 * t01);
                    float d10 = ex2f(-t10 * t10), d11 = ex2f(-t11 * t11);
                    wh[m][2*p]   = h2mul(e0, pack_h2(d00, d01));
                    wh[m][2*p+1] = h2mul(e1, pack_h2(d10, d11));
                }
            }
            #pragma unroll
            for (int jg = 0; jg < 4; ++jg) {
                int rr = 64 * ni + 16 * kt2 + lrow;
                uint32_t off = sw(rr, 2 * jg + luni);
                uint32_t t0, t1, t2, t3;
                LDSM_X4T(t0, t1, t2, t3, kbuf + KB_VH + off);
                #pragma unroll
                for (int m = 0; m < 2; ++m) {
                    MMA16816(Oacc[m][2*jg],   wh[m], t0, t1);
                    MMA16816(Oacc[m][2*jg+1], wh[m], t2, t3);
                }
            }
        }
        #pragma unroll
        for (int m = 0; m < 2; ++m)
            #pragma unroll
            for (int h = 0; h < 2; ++h) {
                half2 v = *reinterpret_cast<half2*>(&lh[m][h]);
                float2 f = __half22float2(v);
                lacc[m][h] += f.x + f.y;
            }

        if (it & 1) { CP_WAIT0(); __syncthreads(); }
    }
    CP_WAIT0();
    __syncthreads();

    // ---- reduce l across lanes sharing a row ----
    #pragma unroll
    for (int m = 0; m < 2; ++m)
        #pragma unroll
        for (int h = 0; h < 2; ++h) {
            float v = lacc[m][h];
            v += __shfl_xor_sync(0xFFFFFFFFu, v, 1);
            v += __shfl_xor_sync(0xFFFFFFFFu, v, 2);
            if ((lane & 3) == 0) {
                int row = 32 * mi + 16 * m + 8 * h + (lane >> 2);
                sts32(sb + SM_L + ni * 512 + row * 4, v);
            }
        }

    // ---- N-half 1 exports O partials to smem ----
    if (ni == 1) {
        #pragma unroll
        for (int m = 0; m < 2; ++m)
            #pragma unroll
            for (int nt = 0; nt < 8; ++nt) {
                int rl = 16 * m + (lane >> 2);
                int c  = 8 * nt + 2 * (lane & 3);
                uint32_t a0 = sb + SM_OX + (((mi * 32 + rl) * OXS) + c) * 4;
                sts64f(a0, Oacc[m][nt][0], Oacc[m][nt][1]);
                uint32_t a1 = sb + SM_OX + (((mi * 32 + rl + 8) * OXS) + c) * 4;
                sts64f(a1, Oacc[m][nt][2], Oacc[m][nt][3]);
            }
    }
    __syncthreads();

    // ---- N-half 0 combines, normalizes, writes gmem ----
    if (ni == 0) {
        #pragma unroll
        for (int m = 0; m < 2; ++m) {
            int rl  = 16 * m + (lane >> 2);
            int rg0 = 32 * mi + rl;
            float inv0 = 1.0f / (lds32(sb + SM_L + rg0 * 4) + lds32(sb + SM_L + 512 + rg0 * 4));
            float inv1 = 1.0f / (lds32(sb + SM_L + (rg0 + 8) * 4) + lds32(sb + SM_L + 512 + (rg0 + 8) * 4));
            #pragma unroll
            for (int nt = 0; nt < 8; ++nt) {
                int c = 8 * nt + 2 * (lane & 3);
                float2 p0 = lds64f(sb + SM_OX + (((mi * 32 + rl) * OXS) + c) * 4);
                float2 p1 = lds64f(sb + SM_OX + (((mi * 32 + rl + 8) * OXS) + c) * 4);
                float2* og0 = reinterpret_cast<float2*>(
                    O + ((size_t)bh * Ss + q0 + rg0) * 64 + c);
                float2* og1 = reinterpret_cast<float2*>(
                    O + ((size_t)bh * Ss + q0 + rg0 + 8) * 64 + c);
                *og0 = make_float2((Oacc[m][nt][0] + p0.x) * inv0,
                                   (Oacc[m][nt][1] + p0.y) * inv0);
                *og1 = make_float2((Oacc[m][nt][2] + p1.x) * inv1,
                                   (Oacc[m][nt][3] + p1.y) * inv1);
            }
        }
    }
}

} // namespace

extern "C" void kernel_launch(void* const* d_in, const int* in_sizes, int n_in,
                              void* d_out, int out_size)
{
    const float* Q = (const float*)d_in[0];
    const float* K = (const float*)d_in[1];
    const float* V = (const float*)d_in[2];
    const int*   mask = (const int*)d_in[3];
    float* O = (float*)d_out;

    scan_kernel<<<4, 1024>>>(mask);
    init_kernel<<<(4 * SROWS + 255) / 256, 256>>>();
    gather_kernel<<<dim3(Ss / 8, BH), 256>>>(K, V, mask);
    pad_kernel<<<BH, 1024>>>();

    cudaFuncSetAttribute(attn_hmma_kernel, cudaFuncAttributeMaxDynamicSharedMemorySize, SM_TOTAL);
    dim3 grid(Ss / BM, BH);
    attn_hmma_kernel<<<grid, NTHR, SM_TOTAL>>>(Q, O);
}